// round 6
// baseline (speedup 1.0000x reference)
#include <cuda_runtime.h>
#include <cuda_bf16.h>
#include <cstdint>

#define NB      1024
#define NNODES  10000
#define NROOTS  4
#define MNODES  (NNODES - NROOTS)   // 9996
#define NCONF   16
#define NPAD    10016               // padded node count

// Interleaved transposed bit-pack: g_evi[(rgq*NPAD + node)*4 + q] has bit r =
// evidence[(rgq*4+q)*32 + r][node].  uint4 per node = 128 batch rows.
__device__ uint32_t g_evi[8 * NPAD * 4];     // 1.28 MB
__device__ float    g_sig[MNODES * NCONF];   // 640 KB pre-sigmoided CPT

// ---------------------------------------------------------------------------
// Kernel A (fused pack + sigmoid). Pack: warp tile = 64 nodes x 32 rows.
// Lane owns 2 nodes; builds 2 bit-words from 32 coalesced int2 row loads.
// ---------------------------------------------------------------------------
#define PACK_TILES   157                    // ceil(10000/64)
#define PACK_WARPS   (PACK_TILES * 32)      // x 32 row-groups
#define PACK_BLOCKS  (PACK_WARPS / 8)       // 628
#define SIG_TOTAL    (MNODES * NCONF / 4)   // 39984 float4
#define SIG_BLOCKS   ((SIG_TOTAL + 255) / 256)

__global__ __launch_bounds__(256)
void pack_sig_kernel(const int* __restrict__ ev, const float4* __restrict__ cpt4) {
    if (blockIdx.x >= PACK_BLOCKS) {
        int idx = (blockIdx.x - PACK_BLOCKS) * 256 + threadIdx.x;
        if (idx < SIG_TOTAL) {
            float4 x = cpt4[idx];
            float4 y;
            y.x = 1.0f / (1.0f + __expf(-x.x));
            y.y = 1.0f / (1.0f + __expf(-x.y));
            y.z = 1.0f / (1.0f + __expf(-x.z));
            y.w = 1.0f / (1.0f + __expf(-x.w));
            ((float4*)g_sig)[idx] = y;
        }
        return;
    }

    const int g    = blockIdx.x * 8 + (threadIdx.x >> 5);
    const int lane = threadIdx.x & 31;
    const int rg   = g & 31;
    const int tile = g >> 5;                         // 0..156
    const int n    = tile * 64 + lane * 2;
    if (n >= NNODES) return;                         // NNODES even: pairs never straddle

    const int* __restrict__ base = ev + (size_t)(rg * 32) * NNODES + n;
    uint32_t a0 = 0, a1 = 0;
    #pragma unroll 8
    for (int r = 0; r < 32; r++) {
        int2 v = *(const int2*)(base + (size_t)r * NNODES);
        a0 |= (uint32_t)(v.x & 1) << r;
        a1 |= (uint32_t)(v.y & 1) << r;
    }
    uint32_t* dst = g_evi + ((size_t)(rg >> 2) * NPAD + n) * 4 + (rg & 3);
    dst[0] = a0;
    dst[4] = a1;
}

// ---------------------------------------------------------------------------
// Kernel B: main. grid=(79, 8), block=128. Thread owns node i, row-quad rgq
// (128 batch rows). 4 scattered LDG.128 fetch parent bits for all 128 rows;
// 16 sigmoids staged conf-major in smem (conflict-free); 128 outputs.
// ---------------------------------------------------------------------------
#define THREADS 128

__global__ __launch_bounds__(THREADS)
void bayes_main(const int4*  __restrict__ parents4,
                const float* __restrict__ root_logits,
                float*       __restrict__ out) {
    __shared__ float slot[NCONF * THREADS];          // 8 KB, conf-major

    const int rgq = blockIdx.y;                      // 0..7
    const int b0  = rgq * 128;
    const int tid = threadIdx.x;
    const int i   = blockIdx.x * THREADS + tid;

    // Roots: first node-tile writes 128 rows x 4 roots
    if (blockIdx.x == 0) {
        #pragma unroll
        for (int r = 0; r < NROOTS; r++) {
            float x = root_logits[r];
            out[(size_t)(b0 + tid) * NNODES + r] = 1.0f / (1.0f + __expf(-x));
        }
    }
    if (i >= MNODES) return;

    const int4 p = parents4[i];
    const uint4* __restrict__ evi4 = (const uint4*)(g_evi + (size_t)rgq * NPAD * 4);
    const uint4 wa = evi4[p.x];
    const uint4 wb = evi4[p.y];
    const uint4 wc = evi4[p.z];
    const uint4 wd = evi4[p.w];

    // Stage 16 pre-sigmoided values, conf-major (private column, no sync)
    const float4* __restrict__ srow = (const float4*)(g_sig + (size_t)i * NCONF);
    #pragma unroll
    for (int j = 0; j < 4; j++) {
        float4 v = srow[j];
        slot[(j * 4 + 0) * THREADS + tid] = v.x;
        slot[(j * 4 + 1) * THREADS + tid] = v.y;
        slot[(j * 4 + 2) * THREADS + tid] = v.z;
        slot[(j * 4 + 3) * THREADS + tid] = v.w;
    }

    float* obase = out + (size_t)b0 * NNODES + NROOTS + i;
    #pragma unroll
    for (int q = 0; q < 4; q++) {
        const uint32_t x0 = (&wa.x)[q];
        const uint32_t x1 = (&wb.x)[q];
        const uint32_t x2 = (&wc.x)[q];
        const uint32_t x3 = (&wd.x)[q];
        float* orow = obase + (size_t)(q * 32) * NNODES;
        #pragma unroll
        for (int r = 0; r < 32; r++) {
            unsigned conf = (((x0 >> r) & 1u) << 3)
                          | (((x1 >> r) & 1u) << 2)
                          | (((x2 >> r) & 1u) << 1)
                          |  ((x3 >> r) & 1u);
            orow[(size_t)r * NNODES] = slot[conf * THREADS + tid];
        }
    }
}

// ---------------------------------------------------------------------------
extern "C" void kernel_launch(void* const* d_in, const int* in_sizes, int n_in,
                              void* d_out, int out_size) {
    const int*    ev      = (const int*)d_in[0];
    const int4*   parents = (const int4*)d_in[1];
    const float*  roots   = (const float*)d_in[2];
    const float4* cpt4    = (const float4*)d_in[3];
    float*        out     = (float*)d_out;

    pack_sig_kernel<<<PACK_BLOCKS + SIG_BLOCKS, 256>>>(ev, cpt4);

    dim3 gmain((MNODES + THREADS - 1) / THREADS, 8);   // (79, 8)
    bayes_main<<<gmain, THREADS>>>(parents, roots, out);
}